// round 15
// baseline (speedup 1.0000x reference)
#include <cuda_runtime.h>
#include <cuda_fp16.h>
#include <math.h>
#include <stdint.h>

// ============================================================================
// FBP as one dense GEMM (mma.sync fp16 path; tcgen05 unavailable in compute_103)
//   out[pixel, slice] = sum_k G[pixel,k] * F[slice,k],  K = 8 views * 128 det
// fp16 single product (11-bit mantissa -> ~4e-4 rel err), fp32 accumulate.
// R15: (1) gmat packs per-angle tables into one float4 + unroll 4;
//      (2) GEMM goes persistent (grid 296, inner chunk pipeline unchanged).
// Fork-join capture (gmat || filter) retained.
// ============================================================================

#define NCHUNK 16                  // K chunks of 64
#define STAGE_B 32768              // A 16K + B 16K
#define NSTAGE 3
#define GEMM_SMEM (NSTAGE*STAGE_B + 1024)
#define GEMM_GRID 296              // 2 CTAs/SM, persistent

#define VSTRIDE 132                // padded view stride inside a pixel row (floats)
#define GROW 1060                  // pixel row stride = 8*132 + 4 (bank-staggered)
#define GMAT_SMEM ((32 * GROW + 128) * 4)   // + per-thread scratch

// Pre-swizzled blocked operands (fp16):
//  dG: [128 ptiles][16 kchunks][128 rows x 64 cols, SW128 128B rows]
//  dF: [ 16 stiles][16 kchunks][128 rows x 64 cols, SW128 128B rows]
__device__ __half dG[16384*1024];
__device__ __half dF[2048*1024];

struct Ptrs { const float* p[8]; };

__host__ __device__ __forceinline__ uint32_t swz(uint32_t b) {      // SW128
    return b ^ ((b >> 3) & 0x70);
}

static __device__ __forceinline__ uint32_t f16x2(float hi, float lo) {
    uint32_t r;
    asm("cvt.rn.f16x2.f32 %0, %1, %2;" : "=r"(r) : "f"(hi), "f"(lo));
    return r;                                  // low 16 bits = lo arg
}

// ---------------------------------------------------------------------------
// F: ramp-filter, fp16, blocked+swizzled. 4 slices per CTA (512 threads).
__global__ __launch_bounds__(512) void fbp_filter(Ptrs P) {
    __shared__ float raws[4][8][132];      // 16B-aligned rows for float4 loads
    __shared__ float h2s[256];
    __shared__ float hp[128][4];
    const int tid = threadIdx.x;
    const float PI = 3.14159265358979323846f;

    // partial sums of h[n] = (1/128^2) sum_k min(k,128-k) cos(2 pi k n/128) * pi/256
    {
        int n = tid >> 2, sub = tid & 3;
        float acc = 0.0f;
        int k0 = sub * 32;
        for (int k = k0; k < k0 + 32; k++) {
            float ramp = (float)(k < 64 ? k : 128 - k);
            int ph = (k * n) & 127;
            acc += ramp * cosf((float)ph * (2.0f * PI / 128.0f));
        }
        hp[n][sub] = acc;
    }

    const int sl = tid >> 7;               // local slice 0..3
    const int lt = tid & 127;
    const int s = blockIdx.x * 4 + sl;     // slice 0..2047
    {
        int v = lt >> 4, w0 = (lt & 15) * 8;
        const float* src = P.p[v] + (size_t)s * 128 + w0;
        #pragma unroll
        for (int j = 0; j < 8; j++) raws[sl][v][w0 + j] = src[j];
    }
    __syncthreads();
    if (tid < 128) {
        float hv = (hp[tid][0] + hp[tid][1] + hp[tid][2] + hp[tid][3])
                 * (1.0f / (128.0f * 128.0f)) * (PI / 256.0f);
        h2s[tid] = hv;
        h2s[tid + 128] = hv;
    }
    __syncthreads();

    const int v  = lt >> 4;
    const int t0 = (lt & 15) * 8;
    float acc[8];
    #pragma unroll
    for (int j = 0; j < 8; j++) acc[j] = 0.0f;

    float hv[15];
    #pragma unroll
    for (int k = 0; k < 15; k++) hv[k] = h2s[t0 + 121 + k];

    const float* rrow = raws[sl][v];
    #pragma unroll
    for (int wb = 0; wb < 16; wb++) {
        float4 ra = *(const float4*)(rrow + wb * 8);
        float4 rb = *(const float4*)(rrow + wb * 8 + 4);
        float r[8] = {ra.x, ra.y, ra.z, ra.w, rb.x, rb.y, rb.z, rb.w};
        #pragma unroll
        for (int wi = 0; wi < 8; wi++)
            #pragma unroll
            for (int j = 0; j < 8; j++)
                acc[j] = fmaf(r[wi], hv[7 + j - wi], acc[j]);
        if (wb < 15) {
            #pragma unroll
            for (int k = 14; k >= 8; k--) hv[k] = hv[k - 8];
            int base = t0 + 121 - (wb + 1) * 8;
            #pragma unroll
            for (int k = 0; k < 8; k++) hv[k] = h2s[base + k];
        }
    }

    uint32_t hb[4];
    #pragma unroll
    for (int j = 0; j < 4; j++) hb[j] = f16x2(acc[2*j+1], acc[2*j]);

    const int r = s & 127, stile = s >> 7;
    int kv0 = v * 128 + t0;
    int kc = kv0 >> 6, c0 = kv0 & 63;
    uint32_t ob = (uint32_t)(stile * 16 + kc) * 8192u + (swz((uint32_t)(r * 128 + c0 * 2)) >> 1);
    *(uint4*)(dF + ob) = make_uint4(hb[0], hb[1], hb[2], hb[3]);
}

// ---------------------------------------------------------------------------
// G: branch-free bilinear scatter; packed per-angle table (one LDS.128/angle).
__global__ __launch_bounds__(128) void fbp_gmat() {
    extern __shared__ float g[];           // 32*GROW + 128 floats
    __shared__ float4 tab[128];            // {cos, sin, wv, v0|v1<<16}
    const int tid = threadIdx.x;
    const float PI = 3.14159265358979323846f;

    {
        int a = tid;
        float sn, cs;
        sincosf((float)a * (PI / 128.0f), &sn, &cs);
        float cv = ((float)a + 0.5f) * (1.0f / 16.0f) - 0.5f;
        cv = fminf(fmaxf(cv, 0.0f), 7.0f);
        int v0 = (int)cv;
        int v1 = min(v0 + 1, 7);
        tab[a] = make_float4(cs, sn, cv - (float)v0,
                             __int_as_float(v0 | (v1 << 16)));
    }
    float4* g4 = (float4*)g;               // (32*GROW+128) divisible by 4
    for (int i = tid; i < (32 * GROW + 128) / 4; i += 128)
        g4[i] = make_float4(0, 0, 0, 0);
    __syncthreads();

    {
        const int px = tid >> 2, q = tid & 3;
        const int dv = q & 1, dt = q >> 1;
        const int p = blockIdx.x * 32 + px;
        const float x = (float)(p & 127) - 63.5f;
        const float y = (float)(p >> 7)  - 63.5f;
        float* gp = g + px * GROW;
        float* scratch = g + 32 * GROW + tid;

        #pragma unroll 4
        for (int a = 0; a < 128; a++) {
            float4 t4 = tab[a];
            float tt = fmaf(y, t4.y, fmaf(x, t4.x, 63.5f));
            tt = fminf(fmaxf(tt, 0.0f), 127.0f);
            int   t0 = (int)tt;
            int   t1 = min(t0 + 1, 127);
            float w1 = tt - (float)t0;
            int vp = __float_as_int(t4.w);
            int v0 = vp & 0xffff, v1 = vp >> 16;
            float wv = t4.z;
            float wvt = dv ? wv : 1.0f - wv;
            float wtt = dt ? w1 : 1.0f - w1;
            int vs = dv ? v1 : v0;
            int ts = dt ? t1 : t0;
            bool bad = ((dv != 0) & (v0 == v1)) | ((dt != 0) & (t0 == t1));
            float* addr = bad ? scratch : (gp + vs * VSTRIDE + ts);
            *addr += wvt * wtt;
        }
    }
    __syncthreads();

    for (int u = tid; u < 4096; u += 128) {
        int pl = u >> 7, cu = u & 127;
        int v = cu >> 4, tg = (cu & 15) * 8;
        int kv0 = cu * 8;
        int kc = kv0 >> 6, c0 = kv0 & 63;
        int p = blockIdx.x * 32 + pl;
        int pt = p >> 7, r = p & 127;
        const float* src = g + pl * GROW + v * VSTRIDE + tg;
        uint32_t hb[4];
        #pragma unroll
        for (int j = 0; j < 4; j++) hb[j] = f16x2(src[2*j+1], src[2*j]);
        uint32_t ob = (uint32_t)(pt * 16 + kc) * 8192u + (swz((uint32_t)(r * 128 + c0 * 2)) >> 1);
        *(uint4*)(dG + ob) = make_uint4(hb[0], hb[1], hb[2], hb[3]);
    }
}

// ---------------------------------------------------------------------------
static __device__ __forceinline__ uint32_t smem_u32(const void* p) {
    uint32_t a;
    asm("{ .reg .u64 t; cvta.to.shared.u64 t, %1; cvt.u32.u64 %0, t; }" : "=r"(a) : "l"(p));
    return a;
}
static __device__ __forceinline__ void cp16(uint32_t dst, const void* src) {
    asm volatile("cp.async.cg.shared.global [%0], [%1], 16;" :: "r"(dst), "l"(src));
}
#define LDSM4(r, addr) \
    asm volatile("ldmatrix.sync.aligned.m8n8.x4.shared.b16 {%0,%1,%2,%3}, [%4];" \
        : "=r"((r)[0]), "=r"((r)[1]), "=r"((r)[2]), "=r"((r)[3]) : "r"(addr))
#define MMA16816F16(c, a, b0, b1) \
    asm volatile("mma.sync.aligned.m16n8k16.row.col.f32.f16.f16.f32 " \
        "{%0,%1,%2,%3}, {%4,%5,%6,%7}, {%8,%9}, {%0,%1,%2,%3};" \
        : "+f"((c)[0]), "+f"((c)[1]), "+f"((c)[2]), "+f"((c)[3]) \
        : "r"((a)[0]), "r"((a)[1]), "r"((a)[2]), "r"((a)[3]), "r"(b0), "r"(b1))

__global__ void __launch_bounds__(256, 2) fbp_gemm(float* __restrict__ out) {
    extern __shared__ unsigned char smraw[];
    const uint32_t sb0 = smem_u32(smraw);
    const uint32_t sb  = (sb0 + 1023u) & ~1023u;
    float* Cp = (float*)(smraw + (sb - sb0));

    const int tid = threadIdx.x, wid = tid >> 5, lane = tid & 31;

    const int mbase = (wid >> 2) * 64;             // 2 M blocks of 64
    const int nbase = (wid & 3) * 32;              // 4 N blocks of 32

    const uint32_t xmask = (uint32_t)(lane & 7) << 4;
    const uint32_t arow  = (uint32_t)(lane & 15);
    const uint32_t akoff = (uint32_t)((lane >> 4) << 4);
    const uint32_t brow  = (uint32_t)((lane & 7) | ((lane & 16) >> 1));
    const uint32_t bkoff = (uint32_t)((lane & 8) << 1);

    for (int tile = blockIdx.x; tile < 2048; tile += GEMM_GRID) {
        const int ptile = tile & 127;              // fastest -> B shared among peers
        const int stile = tile >> 7;
        const __half* gA = dG + (size_t)ptile * 131072;
        const __half* gB = dF + (size_t)stile * 131072;

        float C[4][4][4];
        #pragma unroll
        for (int i = 0; i < 4; i++)
            #pragma unroll
            for (int j = 0; j < 4; j++)
                #pragma unroll
                for (int q = 0; q < 4; q++) C[i][j][q] = 0.0f;

        auto copy_chunk = [&](int c) {
            uint32_t st = sb + (uint32_t)(c % NSTAGE) * STAGE_B;
            #pragma unroll
            for (int p = 0; p < 4; p++) {
                cp16(st +         (uint32_t)(p * 4096 + tid * 16),
                     (const char*)(gA + c * 8192) + p * 4096 + tid * 16);
                cp16(st + 16384 + (uint32_t)(p * 4096 + tid * 16),
                     (const char*)(gB + c * 8192) + p * 4096 + tid * 16);
            }
            asm volatile("cp.async.commit_group;" ::: "memory");
        };

        copy_chunk(0);
        copy_chunk(1);

        for (int c = 0; c < NCHUNK; c++) {
            if (c < NCHUNK - 1) asm volatile("cp.async.wait_group 1;" ::: "memory");
            else                asm volatile("cp.async.wait_group 0;" ::: "memory");
            __syncthreads();

            const uint32_t st = sb + (uint32_t)(c % NSTAGE) * STAGE_B;
            const uint32_t aT = st, bT = st + 16384;

            #pragma unroll
            for (int kk = 0; kk < 4; kk++) {
                const uint32_t kA = ((uint32_t)(kk * 32) + akoff) ^ xmask;
                const uint32_t kB = ((uint32_t)(kk * 32) + bkoff) ^ xmask;

                uint32_t ah[4][4], bh[4][2];
                #pragma unroll
                for (int mt = 0; mt < 4; mt++) {
                    uint32_t ro = (uint32_t)(mbase + mt * 16 + arow) * 128u;
                    LDSM4(ah[mt], aT + ro + kA);
                }
                #pragma unroll
                for (int h = 0; h < 2; h++) {
                    uint32_t ro = (uint32_t)(nbase + h * 16 + brow) * 128u;
                    uint32_t rt[4];
                    LDSM4(rt, bT + ro + kB);
                    bh[2*h][0] = rt[0]; bh[2*h][1] = rt[1];
                    bh[2*h+1][0] = rt[2]; bh[2*h+1][1] = rt[3];
                }
                #pragma unroll
                for (int mt = 0; mt < 4; mt++)
                    #pragma unroll
                    for (int nt = 0; nt < 4; nt++)
                        MMA16816F16(C[mt][nt], ah[mt], bh[nt][0], bh[nt][1]);
            }
            __syncthreads();
            if (c + 2 < NCHUNK) copy_chunk(c + 2);
        }

        // Epilogue: transpose C into SMEM as [slice n][pixel m], coalesced out.
        __syncthreads();
        #pragma unroll
        for (int mt = 0; mt < 4; mt++)
            #pragma unroll
            for (int nt = 0; nt < 4; nt++) {
                int m0 = mbase + mt * 16 + (lane >> 2);
                int n0 = nbase + nt * 8 + 2 * (lane & 3);
                Cp[(n0    ) * 132 + m0    ] = C[mt][nt][0];
                Cp[(n0 + 1) * 132 + m0    ] = C[mt][nt][1];
                Cp[(n0    ) * 132 + m0 + 8] = C[mt][nt][2];
                Cp[(n0 + 1) * 132 + m0 + 8] = C[mt][nt][3];
            }
        __syncthreads();

        const int px = (tid & 31) * 4;
        #pragma unroll
        for (int i = 0; i < 16; i++) {
            int n = (tid >> 5) + i * 8;
            float4 v = *(const float4*)(Cp + n * 132 + px);
            *(float4*)(out + (size_t)(stile * 128 + n) * 16384 + ptile * 128 + px) = v;
        }
        __syncthreads();   // protect Cp/stage smem before next tile's copies
    }
}

// ---------------------------------------------------------------------------
extern "C" void kernel_launch(void* const* d_in, const int* in_sizes, int n_in,
                              void* d_out, int out_size) {
    (void)in_sizes; (void)n_in; (void)out_size;
    cudaFuncSetAttribute(fbp_gmat, cudaFuncAttributeMaxDynamicSharedMemorySize, GMAT_SMEM);
    cudaFuncSetAttribute(fbp_gemm, cudaFuncAttributeMaxDynamicSharedMemorySize, GEMM_SMEM);

    Ptrs P;
    for (int i = 0; i < 8; i++) P.p[i] = (const float*)d_in[i];

    // Fork-join: gmat runs on a side stream concurrently with filter.
    cudaStream_t s2;
    cudaEvent_t eFork, eJoin;
    bool forked = (cudaStreamCreateWithFlags(&s2, cudaStreamNonBlocking) == cudaSuccess) &&
                  (cudaEventCreateWithFlags(&eFork, cudaEventDisableTiming) == cudaSuccess) &&
                  (cudaEventCreateWithFlags(&eJoin, cudaEventDisableTiming) == cudaSuccess);

    if (forked) {
        cudaEventRecord(eFork, 0);              // legacy (captured) stream
        cudaStreamWaitEvent(s2, eFork, 0);
        fbp_gmat<<<512, 128, GMAT_SMEM, s2>>>();
        cudaEventRecord(eJoin, s2);
        fbp_filter<<<512, 512>>>(P);
        cudaStreamWaitEvent(0, eJoin, 0);       // join before GEMM
    } else {
        fbp_filter<<<512, 512>>>(P);
        fbp_gmat<<<512, 128, GMAT_SMEM>>>();
    }
    fbp_gemm<<<GEMM_GRID, 256, GEMM_SMEM>>>((float*)d_out);
}

// round 16
// speedup vs baseline: 1.0598x; 1.0598x over previous
#include <cuda_runtime.h>
#include <cuda_fp16.h>
#include <math.h>
#include <stdint.h>

// ============================================================================
// FBP as one dense GEMM (mma.sync fp16 path; tcgen05 unavailable in compute_103)
//   out[pixel, slice] = sum_k G[pixel,k] * F[slice,k],  K = 8 views * 128 det
// fp16 single product (11-bit mantissa -> ~4e-4 rel err), fp32 accumulate.
// R16: GEMM reverted to R14 (non-persistent, proven 174.5us). gmat reshaped to
// 8 pixels / 32 threads / 34KB per CTA (grid 2048) -> 6 CTAs/SM instead of 1.
// Fork-join capture (gmat || filter) retained.
// ============================================================================

#define NCHUNK 16                  // K chunks of 64
#define STAGE_B 32768              // A 16K + B 16K
#define NSTAGE 3
#define GEMM_SMEM (NSTAGE*STAGE_B + 1024)

#define VSTRIDE 132                // padded view stride inside a pixel row (floats)
#define GROW 1060                  // pixel row stride (floats); px*1060 mod 32 = 4*px
#define GPIX 8                     // pixels per gmat CTA
#define GMAT_SMEM ((GPIX * GROW + 32) * 4)   // + per-thread scratch (33,920+128 B)

// Pre-swizzled blocked operands (fp16):
//  dG: [128 ptiles][16 kchunks][128 rows x 64 cols, SW128 128B rows]
//  dF: [ 16 stiles][16 kchunks][128 rows x 64 cols, SW128 128B rows]
__device__ __half dG[16384*1024];
__device__ __half dF[2048*1024];

struct Ptrs { const float* p[8]; };

__host__ __device__ __forceinline__ uint32_t swz(uint32_t b) {      // SW128
    return b ^ ((b >> 3) & 0x70);
}

static __device__ __forceinline__ uint32_t f16x2(float hi, float lo) {
    uint32_t r;
    asm("cvt.rn.f16x2.f32 %0, %1, %2;" : "=r"(r) : "f"(hi), "f"(lo));
    return r;                                  // low 16 bits = lo arg
}

// ---------------------------------------------------------------------------
// F: ramp-filter, fp16, blocked+swizzled. 4 slices per CTA (512 threads).
__global__ __launch_bounds__(512) void fbp_filter(Ptrs P) {
    __shared__ float raws[4][8][132];      // 16B-aligned rows for float4 loads
    __shared__ float h2s[256];
    __shared__ float hp[128][4];
    const int tid = threadIdx.x;
    const float PI = 3.14159265358979323846f;

    // partial sums of h[n] = (1/128^2) sum_k min(k,128-k) cos(2 pi k n/128) * pi/256
    {
        int n = tid >> 2, sub = tid & 3;
        float acc = 0.0f;
        int k0 = sub * 32;
        for (int k = k0; k < k0 + 32; k++) {
            float ramp = (float)(k < 64 ? k : 128 - k);
            int ph = (k * n) & 127;
            acc += ramp * cosf((float)ph * (2.0f * PI / 128.0f));
        }
        hp[n][sub] = acc;
    }

    const int sl = tid >> 7;               // local slice 0..3
    const int lt = tid & 127;
    const int s = blockIdx.x * 4 + sl;     // slice 0..2047
    {
        int v = lt >> 4, w0 = (lt & 15) * 8;
        const float* src = P.p[v] + (size_t)s * 128 + w0;
        #pragma unroll
        for (int j = 0; j < 8; j++) raws[sl][v][w0 + j] = src[j];
    }
    __syncthreads();
    if (tid < 128) {
        float hv = (hp[tid][0] + hp[tid][1] + hp[tid][2] + hp[tid][3])
                 * (1.0f / (128.0f * 128.0f)) * (PI / 256.0f);
        h2s[tid] = hv;
        h2s[tid + 128] = hv;
    }
    __syncthreads();

    const int v  = lt >> 4;
    const int t0 = (lt & 15) * 8;
    float acc[8];
    #pragma unroll
    for (int j = 0; j < 8; j++) acc[j] = 0.0f;

    float hv[15];
    #pragma unroll
    for (int k = 0; k < 15; k++) hv[k] = h2s[t0 + 121 + k];

    const float* rrow = raws[sl][v];
    #pragma unroll
    for (int wb = 0; wb < 16; wb++) {
        float4 ra = *(const float4*)(rrow + wb * 8);
        float4 rb = *(const float4*)(rrow + wb * 8 + 4);
        float r[8] = {ra.x, ra.y, ra.z, ra.w, rb.x, rb.y, rb.z, rb.w};
        #pragma unroll
        for (int wi = 0; wi < 8; wi++)
            #pragma unroll
            for (int j = 0; j < 8; j++)
                acc[j] = fmaf(r[wi], hv[7 + j - wi], acc[j]);
        if (wb < 15) {
            #pragma unroll
            for (int k = 14; k >= 8; k--) hv[k] = hv[k - 8];
            int base = t0 + 121 - (wb + 1) * 8;
            #pragma unroll
            for (int k = 0; k < 8; k++) hv[k] = h2s[base + k];
        }
    }

    uint32_t hb[4];
    #pragma unroll
    for (int j = 0; j < 4; j++) hb[j] = f16x2(acc[2*j+1], acc[2*j]);

    const int r = s & 127, stile = s >> 7;
    int kv0 = v * 128 + t0;
    int kc = kv0 >> 6, c0 = kv0 & 63;
    uint32_t ob = (uint32_t)(stile * 16 + kc) * 8192u + (swz((uint32_t)(r * 128 + c0 * 2)) >> 1);
    *(uint4*)(dF + ob) = make_uint4(hb[0], hb[1], hb[2], hb[3]);
}

// ---------------------------------------------------------------------------
// G: branch-free bilinear scatter, 8 pixels / 32 threads per CTA (grid 2048).
// thread = (pixel, corner); 1 RMW per angle; dup corners -> private scratch.
__global__ __launch_bounds__(32) void fbp_gmat() {
    extern __shared__ float g[];           // GPIX*GROW + 32 floats
    __shared__ float4 tab[128];            // {cos, sin, wv, v0|v1<<16}
    const int tid = threadIdx.x;
    const float PI = 3.14159265358979323846f;

    // per-angle table: 32 threads x 4 angles each
    #pragma unroll
    for (int i = 0; i < 4; i++) {
        int a = tid + i * 32;
        float sn, cs;
        sincosf((float)a * (PI / 128.0f), &sn, &cs);
        float cv = ((float)a + 0.5f) * (1.0f / 16.0f) - 0.5f;
        cv = fminf(fmaxf(cv, 0.0f), 7.0f);
        int v0 = (int)cv;
        int v1 = min(v0 + 1, 7);
        tab[a] = make_float4(cs, sn, cv - (float)v0,
                             __int_as_float(v0 | (v1 << 16)));
    }
    float4* g4 = (float4*)g;               // (GPIX*GROW+32) divisible by 4
    for (int i = tid; i < (GPIX * GROW + 32) / 4; i += 32)
        g4[i] = make_float4(0, 0, 0, 0);
    __syncthreads();

    {
        const int px = tid >> 2, q = tid & 3;
        const int dv = q & 1, dt = q >> 1;
        const int p = blockIdx.x * GPIX + px;
        const float x = (float)(p & 127) - 63.5f;
        const float y = (float)(p >> 7)  - 63.5f;
        float* gp = g + px * GROW;
        float* scratch = g + GPIX * GROW + tid;

        #pragma unroll 4
        for (int a = 0; a < 128; a++) {
            float4 t4 = tab[a];
            float tt = fmaf(y, t4.y, fmaf(x, t4.x, 63.5f));
            tt = fminf(fmaxf(tt, 0.0f), 127.0f);
            int   t0 = (int)tt;
            int   t1 = min(t0 + 1, 127);
            float w1 = tt - (float)t0;
            int vp = __float_as_int(t4.w);
            int v0 = vp & 0xffff, v1 = vp >> 16;
            float wv = t4.z;
            float wvt = dv ? wv : 1.0f - wv;
            float wtt = dt ? w1 : 1.0f - w1;
            int vs = dv ? v1 : v0;
            int ts = dt ? t1 : t0;
            bool bad = ((dv != 0) & (v0 == v1)) | ((dt != 0) & (t0 == t1));
            float* addr = bad ? scratch : (gp + vs * VSTRIDE + ts);
            *addr += wvt * wtt;
        }
    }
    __syncthreads();

    // writeback: units of 8 consecutive k (within one view segment)
    for (int u = tid; u < GPIX * 128; u += 32) {
        int pl = u >> 7, cu = u & 127;
        int v = cu >> 4, tg = (cu & 15) * 8;
        int kv0 = cu * 8;
        int kc = kv0 >> 6, c0 = kv0 & 63;
        int p = blockIdx.x * GPIX + pl;
        int pt = p >> 7, r = p & 127;
        const float* src = g + pl * GROW + v * VSTRIDE + tg;
        uint32_t hb[4];
        #pragma unroll
        for (int j = 0; j < 4; j++) hb[j] = f16x2(src[2*j+1], src[2*j]);
        uint32_t ob = (uint32_t)(pt * 16 + kc) * 8192u + (swz((uint32_t)(r * 128 + c0 * 2)) >> 1);
        *(uint4*)(dG + ob) = make_uint4(hb[0], hb[1], hb[2], hb[3]);
    }
}

// ---------------------------------------------------------------------------
static __device__ __forceinline__ uint32_t smem_u32(const void* p) {
    uint32_t a;
    asm("{ .reg .u64 t; cvta.to.shared.u64 t, %1; cvt.u32.u64 %0, t; }" : "=r"(a) : "l"(p));
    return a;
}
static __device__ __forceinline__ void cp16(uint32_t dst, const void* src) {
    asm volatile("cp.async.cg.shared.global [%0], [%1], 16;" :: "r"(dst), "l"(src));
}
#define LDSM4(r, addr) \
    asm volatile("ldmatrix.sync.aligned.m8n8.x4.shared.b16 {%0,%1,%2,%3}, [%4];" \
        : "=r"((r)[0]), "=r"((r)[1]), "=r"((r)[2]), "=r"((r)[3]) : "r"(addr))
#define MMA16816F16(c, a, b0, b1) \
    asm volatile("mma.sync.aligned.m16n8k16.row.col.f32.f16.f16.f32 " \
        "{%0,%1,%2,%3}, {%4,%5,%6,%7}, {%8,%9}, {%0,%1,%2,%3};" \
        : "+f"((c)[0]), "+f"((c)[1]), "+f"((c)[2]), "+f"((c)[3]) \
        : "r"((a)[0]), "r"((a)[1]), "r"((a)[2]), "r"((a)[3]), "r"(b0), "r"(b1))

__global__ void __launch_bounds__(256, 2) fbp_gemm(float* __restrict__ out) {
    extern __shared__ unsigned char smraw[];
    const uint32_t sb0 = smem_u32(smraw);
    const uint32_t sb  = (sb0 + 1023u) & ~1023u;
    float* Cp = (float*)(smraw + (sb - sb0));

    const int tid = threadIdx.x, wid = tid >> 5, lane = tid & 31;
    const int ptile = blockIdx.x;                  // 0..127
    const int stile = blockIdx.y;                  // 0..15

    const __half* gA = dG + (size_t)ptile * 131072;
    const __half* gB = dF + (size_t)stile * 131072;

    const int mbase = (wid >> 2) * 64;             // 2 M blocks of 64
    const int nbase = (wid & 3) * 32;              // 4 N blocks of 32

    const uint32_t xmask = (uint32_t)(lane & 7) << 4;
    const uint32_t arow  = (uint32_t)(lane & 15);
    const uint32_t akoff = (uint32_t)((lane >> 4) << 4);
    const uint32_t brow  = (uint32_t)((lane & 7) | ((lane & 16) >> 1));
    const uint32_t bkoff = (uint32_t)((lane & 8) << 1);

    float C[4][4][4];
    #pragma unroll
    for (int i = 0; i < 4; i++)
        #pragma unroll
        for (int j = 0; j < 4; j++)
            #pragma unroll
            for (int q = 0; q < 4; q++) C[i][j][q] = 0.0f;

    auto copy_chunk = [&](int c) {
        uint32_t st = sb + (uint32_t)(c % NSTAGE) * STAGE_B;
        #pragma unroll
        for (int p = 0; p < 4; p++) {
            cp16(st +         (uint32_t)(p * 4096 + tid * 16),
                 (const char*)(gA + c * 8192) + p * 4096 + tid * 16);
            cp16(st + 16384 + (uint32_t)(p * 4096 + tid * 16),
                 (const char*)(gB + c * 8192) + p * 4096 + tid * 16);
        }
        asm volatile("cp.async.commit_group;" ::: "memory");
    };

    copy_chunk(0);
    copy_chunk(1);

    for (int c = 0; c < NCHUNK; c++) {
        if (c < NCHUNK - 1) asm volatile("cp.async.wait_group 1;" ::: "memory");
        else                asm volatile("cp.async.wait_group 0;" ::: "memory");
        __syncthreads();

        const uint32_t st = sb + (uint32_t)(c % NSTAGE) * STAGE_B;
        const uint32_t aT = st, bT = st + 16384;

        #pragma unroll
        for (int kk = 0; kk < 4; kk++) {
            const uint32_t kA = ((uint32_t)(kk * 32) + akoff) ^ xmask;
            const uint32_t kB = ((uint32_t)(kk * 32) + bkoff) ^ xmask;

            uint32_t ah[4][4], bh[4][2];
            #pragma unroll
            for (int mt = 0; mt < 4; mt++) {
                uint32_t ro = (uint32_t)(mbase + mt * 16 + arow) * 128u;
                LDSM4(ah[mt], aT + ro + kA);
            }
            #pragma unroll
            for (int h = 0; h < 2; h++) {
                uint32_t ro = (uint32_t)(nbase + h * 16 + brow) * 128u;
                uint32_t rt[4];
                LDSM4(rt, bT + ro + kB);
                bh[2*h][0] = rt[0]; bh[2*h][1] = rt[1];
                bh[2*h+1][0] = rt[2]; bh[2*h+1][1] = rt[3];
            }
            #pragma unroll
            for (int mt = 0; mt < 4; mt++)
                #pragma unroll
                for (int nt = 0; nt < 4; nt++)
                    MMA16816F16(C[mt][nt], ah[mt], bh[nt][0], bh[nt][1]);
        }
        __syncthreads();
        if (c + 2 < NCHUNK) copy_chunk(c + 2);
    }

    // Epilogue: transpose C into SMEM as [slice n][pixel m], then coalesced out.
    __syncthreads();
    #pragma unroll
    for (int mt = 0; mt < 4; mt++)
        #pragma unroll
        for (int nt = 0; nt < 4; nt++) {
            int m0 = mbase + mt * 16 + (lane >> 2);
            int n0 = nbase + nt * 8 + 2 * (lane & 3);
            Cp[(n0    ) * 132 + m0    ] = C[mt][nt][0];
            Cp[(n0 + 1) * 132 + m0    ] = C[mt][nt][1];
            Cp[(n0    ) * 132 + m0 + 8] = C[mt][nt][2];
            Cp[(n0 + 1) * 132 + m0 + 8] = C[mt][nt][3];
        }
    __syncthreads();

    const int px = (tid & 31) * 4;
    #pragma unroll
    for (int i = 0; i < 16; i++) {
        int n = (tid >> 5) + i * 8;
        float4 v = *(const float4*)(Cp + n * 132 + px);
        *(float4*)(out + (size_t)(stile * 128 + n) * 16384 + ptile * 128 + px) = v;
    }
}

// ---------------------------------------------------------------------------
extern "C" void kernel_launch(void* const* d_in, const int* in_sizes, int n_in,
                              void* d_out, int out_size) {
    (void)in_sizes; (void)n_in; (void)out_size;
    cudaFuncSetAttribute(fbp_gmat, cudaFuncAttributeMaxDynamicSharedMemorySize, GMAT_SMEM);
    cudaFuncSetAttribute(fbp_gemm, cudaFuncAttributeMaxDynamicSharedMemorySize, GEMM_SMEM);

    Ptrs P;
    for (int i = 0; i < 8; i++) P.p[i] = (const float*)d_in[i];

    // Fork-join: gmat runs on a side stream concurrently with filter.
    cudaStream_t s2;
    cudaEvent_t eFork, eJoin;
    bool forked = (cudaStreamCreateWithFlags(&s2, cudaStreamNonBlocking) == cudaSuccess) &&
                  (cudaEventCreateWithFlags(&eFork, cudaEventDisableTiming) == cudaSuccess) &&
                  (cudaEventCreateWithFlags(&eJoin, cudaEventDisableTiming) == cudaSuccess);

    if (forked) {
        cudaEventRecord(eFork, 0);              // legacy (captured) stream
        cudaStreamWaitEvent(s2, eFork, 0);
        fbp_gmat<<<2048, 32, GMAT_SMEM, s2>>>();
        cudaEventRecord(eJoin, s2);
        fbp_filter<<<512, 512>>>(P);
        cudaStreamWaitEvent(0, eJoin, 0);       // join before GEMM
    } else {
        fbp_filter<<<512, 512>>>(P);
        fbp_gmat<<<2048, 32, GMAT_SMEM>>>();
    }
    fbp_gemm<<<dim3(128, 16), 256, GEMM_SMEM>>>((float*)d_out);
}